// round 15
// baseline (speedup 1.0000x reference)
#include <cuda_runtime.h>
#include <cuda_bf16.h>
#include <math.h>
#include <stdint.h>

#define Bq 4
#define Tt 4096
#define Dm 1024
#define Ss 64
#define Kk 8
#define Hh 512
#define BT (Bq*Tt)

// ---------------- scratch (__device__ globals) -----------------------------
__device__ float g_m[Dm];
__device__ float g_hs[Ss*Dm];
__device__ float g_c1[Hh];
__device__ float g_gh[128*3*Dm];
__device__ int   g_idx8[BT*Kk];
__device__ float g_w8[BT*Kk];
__device__ unsigned long long g_mask[BT];
__device__ float g_so[Bq*Ss*Dm];
__device__ float g_part[Bq*Ss*8*Dm];
__device__ float g_pw[Bq*Ss*8];
__device__ float g_kpart[2*BT*128];
__device__ float g_kpart2[4*128*3*Dm];

// bf16 hi/lo planes
__device__ uint32_t g_xhi[BT*Dm/2],    g_xlo[BT*Dm/2];
__device__ uint32_t g_w1hi[Hh*2*Dm/2], g_w1lo[Hh*2*Dm/2];
__device__ uint32_t g_w2hi[128*Hh/2],  g_w2lo[128*Hh/2];      // pad rows stay 0
__device__ uint32_t g_whhhi[3*Dm*Dm/2],g_whhlo[3*Dm*Dm/2];
__device__ uint32_t g_wihhi[3*Dm*Dm/2],g_wihlo[3*Dm*Dm/2];
__device__ uint32_t g_wvhi[Dm*Dm/2],   g_wvlo[Dm*Dm/2];
__device__ uint32_t g_wohi[Dm*Dm/2],   g_wolo[Dm*Dm/2];
__device__ uint32_t g_hshi[128*Dm/2],  g_hslo[128*Dm/2];
__device__ uint32_t g_hhi[BT*Hh/2],    g_hlo[BT*Hh/2];
__device__ uint32_t g_gihi[Bq*Ss*Dm/2],g_gilo[Bq*Ss*Dm/2];
__device__ uint32_t g_hnhi[Bq*Ss*Dm/2],g_hnlo[Bq*Ss*Dm/2];
__device__ uint32_t g_svhi[Bq*Ss*Dm/2],g_svlo[Bq*Ss*Dm/2];

__device__ __forceinline__ float gelu_exact(float v) {
    return 0.5f * v * (1.f + erff(v * 0.70710678118654752f));
}
__device__ __forceinline__ float sigm(float v) { return 1.f / (1.f + expf(-v)); }

__device__ __forceinline__ void split2(float a, float b, uint32_t& hi, uint32_t& lo) {
    __nv_bfloat16 ah = __float2bfloat16_rn(a);
    __nv_bfloat16 bh = __float2bfloat16_rn(b);
    float ar = a - __bfloat162float(ah);
    float br = b - __bfloat162float(bh);
    __nv_bfloat16 al = __float2bfloat16_rn(ar);
    __nv_bfloat16 bl = __float2bfloat16_rn(br);
    unsigned short ahu = *(unsigned short*)&ah, bhu = *(unsigned short*)&bh;
    unsigned short alu = *(unsigned short*)&al, blu = *(unsigned short*)&bl;
    hi = (uint32_t)ahu | ((uint32_t)bhu << 16);
    lo = (uint32_t)alu | ((uint32_t)blu << 16);
}

// ---------------- mma helper ------------------------------------------------
__device__ __forceinline__ void mma_bf16(float* d, const uint32_t* a,
                                         uint32_t b0, uint32_t b1)
{
    asm volatile(
        "mma.sync.aligned.m16n8k16.row.col.f32.bf16.bf16.f32 "
        "{%0,%1,%2,%3},{%4,%5,%6,%7},{%8,%9},{%0,%1,%2,%3};\n"
        : "+f"(d[0]), "+f"(d[1]), "+f"(d[2]), "+f"(d[3])
        : "r"(a[0]), "r"(a[1]), "r"(a[2]), "r"(a[3]), "r"(b0), "r"(b1));
}

// ---------------- split-bf16 tensor-core GEMM ------------------------------
// roff: extra row offset (batch chunking). zpitch: split-K z-stride (elements).
__global__ __launch_bounds__(256, 2) void mma_gemm(
    const uint32_t* __restrict__ Ahi, const uint32_t* __restrict__ Alo,
    const uint32_t* __restrict__ Whi, const uint32_t* __restrict__ Wlo,
    const float* __restrict__ bias, float* __restrict__ Cf,
    uint32_t* __restrict__ Chi, uint32_t* __restrict__ Clo,
    int K, int lda, int ldw, int ldc, int act,
    int klen, float* __restrict__ Cpart, int roff, size_t zpitch)
{
    __shared__ uint32_t sA[2][2][8][32][4];
    __shared__ uint32_t sB[2][2][8][32][4];

    int tid = threadIdx.x;
    int lane = tid & 31, warp = tid >> 5;
    int wm = warp >> 2, wn = warp & 3;
    int row0 = roff + blockIdx.y * 128, col0 = blockIdx.x * 128;
    int kbase = Cpart ? blockIdx.z * klen : 0;
    int KK = Cpart ? klen : K;

    float acc[4][4][4];
#pragma unroll
    for (int i = 0; i < 4; i++)
#pragma unroll
        for (int j = 0; j < 4; j++)
#pragma unroll
            for (int r = 0; r < 4; r++) acc[i][j][r] = 0.f;

    uint2 ra[2][2], rb[2][2];
    int r0q = tid >> 2, r1q = (tid + 256) >> 2;
    int kk0 = (tid & 3) * 4;
    int ldua = lda >> 1, lduw = ldw >> 1;

#define LOADG(k0)                                                              \
    {                                                                          \
        size_t a0 = ((size_t)(row0 + r0q) * ldua) + (((k0) + kk0) >> 1);       \
        size_t a1 = ((size_t)(row0 + r1q) * ldua) + (((k0) + kk0) >> 1);       \
        size_t b0 = ((size_t)(col0 + r0q) * lduw) + (((k0) + kk0) >> 1);       \
        size_t b1 = ((size_t)(col0 + r1q) * lduw) + (((k0) + kk0) >> 1);       \
        ra[0][0] = *(const uint2*)(Ahi + a0); ra[0][1] = *(const uint2*)(Alo + a0); \
        ra[1][0] = *(const uint2*)(Ahi + a1); ra[1][1] = *(const uint2*)(Alo + a1); \
        rb[0][0] = *(const uint2*)(Whi + b0); rb[0][1] = *(const uint2*)(Wlo + b0); \
        rb[1][0] = *(const uint2*)(Whi + b1); rb[1][1] = *(const uint2*)(Wlo + b1); \
    }

#define STORES(buf)                                                            \
    {                                                                          \
        _Pragma("unroll")                                                      \
        for (int j = 0; j < 2; j++) {                                          \
            int row = j ? r1q : r0q;                                           \
            int rr = row & 15;                                                 \
            int mt = row >> 4;                                                 \
            int lnA = (rr & 7) * 4 + ((kk0 & 7) >> 1);                         \
            int rgA = (rr >> 3) + 2 * (kk0 >> 3);                              \
            int nt = row >> 3, gg = row & 7;                                   \
            int lnB = gg * 4 + ((kk0 & 7) >> 1);                               \
            int rgB = (nt & 1) * 2 + (kk0 >> 3);                               \
            int ntp = nt >> 1;                                                 \
            _Pragma("unroll")                                                  \
            for (int p = 0; p < 2; p++) {                                      \
                sA[buf][p][mt][lnA][rgA]     = (p ? ra[j][1].x : ra[j][0].x);  \
                sA[buf][p][mt][lnA + 1][rgA] = (p ? ra[j][1].y : ra[j][0].y);  \
                sB[buf][p][ntp][lnB][rgB]     = (p ? rb[j][1].x : rb[j][0].x); \
                sB[buf][p][ntp][lnB + 1][rgB] = (p ? rb[j][1].y : rb[j][0].y); \
            }                                                                  \
        }                                                                      \
    }

    int NK = KK >> 4;
    LOADG(kbase);
    STORES(0);
    __syncthreads();

    for (int ks = 0; ks < NK; ks++) {
        int buf = ks & 1;
        if (ks + 1 < NK) LOADG(kbase + ((ks + 1) << 4));

        uint4 af[4][2];
        uint4 bf[2][2];
#pragma unroll
        for (int mt = 0; mt < 4; mt++) {
            af[mt][0] = *(const uint4*)sA[buf][0][wm * 4 + mt][lane];
            af[mt][1] = *(const uint4*)sA[buf][1][wm * 4 + mt][lane];
        }
#pragma unroll
        for (int i = 0; i < 2; i++) {
            bf[i][0] = *(const uint4*)sB[buf][0][wn * 2 + i][lane];
            bf[i][1] = *(const uint4*)sB[buf][1][wn * 2 + i][lane];
        }
#pragma unroll
        for (int mt = 0; mt < 4; mt++) {
#pragma unroll
            for (int nt = 0; nt < 4; nt++) {
                int ntp = nt >> 1;
                uint32_t bh0, bh1, bl0, bl1;
                if (nt & 1) {
                    bh0 = bf[ntp][0].z; bh1 = bf[ntp][0].w;
                    bl0 = bf[ntp][1].z; bl1 = bf[ntp][1].w;
                } else {
                    bh0 = bf[ntp][0].x; bh1 = bf[ntp][0].y;
                    bl0 = bf[ntp][1].x; bl1 = bf[ntp][1].y;
                }
                mma_bf16(acc[mt][nt], (const uint32_t*)&af[mt][0], bh0, bh1);
                mma_bf16(acc[mt][nt], (const uint32_t*)&af[mt][0], bl0, bl1);
                mma_bf16(acc[mt][nt], (const uint32_t*)&af[mt][1], bh0, bh1);
            }
        }
        if (ks + 1 < NK) {
            __syncthreads();
            STORES(buf ^ 1);
            __syncthreads();
        }
    }

    int g = lane >> 2, t4 = lane & 3;
    int lduc = ldc >> 1;
    if (Cpart) {
        size_t zoff = (size_t)blockIdx.z * zpitch;
#pragma unroll
        for (int mt = 0; mt < 4; mt++) {
            int r0 = row0 + wm * 64 + mt * 16 + g;
#pragma unroll
            for (int nt = 0; nt < 4; nt++) {
                int c = col0 + wn * 32 + nt * 8 + t4 * 2;
                *(float2*)&Cpart[zoff + (size_t)r0 * ldc + c] =
                    make_float2(acc[mt][nt][0], acc[mt][nt][1]);
                *(float2*)&Cpart[zoff + (size_t)(r0 + 8) * ldc + c] =
                    make_float2(acc[mt][nt][2], acc[mt][nt][3]);
            }
        }
        return;
    }
#pragma unroll
    for (int mt = 0; mt < 4; mt++) {
        int r0 = row0 + wm * 64 + mt * 16 + g;
#pragma unroll
        for (int nt = 0; nt < 4; nt++) {
            int c = col0 + wn * 32 + nt * 8 + t4 * 2;
            float bb0 = bias[c], bb1 = bias[c + 1];
            float v0 = acc[mt][nt][0] + bb0;
            float v1 = acc[mt][nt][1] + bb1;
            float v2 = acc[mt][nt][2] + bb0;
            float v3 = acc[mt][nt][3] + bb1;
            if (act) {
                v0 = gelu_exact(v0); v1 = gelu_exact(v1);
                v2 = gelu_exact(v2); v3 = gelu_exact(v3);
            }
            if (Cf) {
                *(float2*)&Cf[(size_t)r0 * ldc + c] = make_float2(v0, v1);
                *(float2*)&Cf[(size_t)(r0 + 8) * ldc + c] = make_float2(v2, v3);
            }
            if (Chi) {
                uint32_t h, l;
                split2(v0, v1, h, l);
                size_t o = (size_t)r0 * lduc + (c >> 1);
                Chi[o] = h; Clo[o] = l;
                split2(v2, v3, h, l);
                o = (size_t)(r0 + 8) * lduc + (c >> 1);
                Chi[o] = h; Clo[o] = l;
            }
        }
    }
#undef LOADG
#undef STORES
}

// ---------------- split-K reduce + epilogue --------------------------------
__global__ __launch_bounds__(256) void reduce_epi(
    const float* __restrict__ part, int nz, size_t zstride,
    const float* __restrict__ bias, float* __restrict__ Cf,
    uint32_t* __restrict__ Chi, uint32_t* __restrict__ Clo,
    int npairs, int N, int act)
{
    int idx = blockIdx.x * 256 + threadIdx.x;
    if (idx >= npairs) return;
    int half = N >> 1;
    int r = idx / half, cp = idx - r * half;
    int c = cp * 2;
    size_t o = (size_t)r * N + c;
    float s0 = 0.f, s1 = 0.f;
    for (int z = 0; z < nz; z++) {
        float2 v = *(const float2*)&part[z * zstride + o];
        s0 += v.x; s1 += v.y;
    }
    s0 += bias[c]; s1 += bias[c + 1];
    if (act) { s0 = gelu_exact(s0); s1 = gelu_exact(s1); }
    if (Cf) *(float2*)&Cf[o] = make_float2(s0, s1);
    if (Chi) {
        uint32_t h, l;
        split2(s0, s1, h, l);
        Chi[(size_t)r * half + cp] = h;
        Clo[(size_t)r * half + cp] = l;
    }
}

// ---------------- fp32 -> hi/lo plane conversion ---------------------------
__global__ void convert_kernel(const float* __restrict__ s,
                               uint32_t* __restrict__ hi, uint32_t* __restrict__ lo,
                               int n4)
{
    int i = blockIdx.x * 256 + threadIdx.x;
    if (i >= n4) return;
    float4 v = ((const float4*)s)[i];
    uint32_t h0, h1, l0, l1;
    split2(v.x, v.y, h0, l0);
    split2(v.z, v.w, h1, l1);
    hi[2*i] = h0; hi[2*i+1] = h1;
    lo[2*i] = l0; lo[2*i+1] = l1;
}

// ---------------- prep (includes hs pad zeroing) ---------------------------
__global__ void prep_kernel(const float* __restrict__ slot_init,
                            const float* __restrict__ slot_scale)
{
    int i = blockIdx.x * 256 + threadIdx.x;
    int d0 = i * 2;
    float s0 = 0.f, s1 = 0.f;
    for (int s = 0; s < Ss; s++) {
        float sc = slot_scale[s];
        float a0 = slot_init[s * Dm + d0] * sc;
        float a1 = slot_init[s * Dm + d0 + 1] * sc;
        g_hs[s * Dm + d0] = a0;
        g_hs[s * Dm + d0 + 1] = a1;
        uint32_t h, l;
        split2(a0, a1, h, l);
        g_hshi[s * (Dm / 2) + i] = h;
        g_hslo[s * (Dm / 2) + i] = l;
        s0 += a0; s1 += a1;
    }
    for (int s = 64; s < 128; s++) {
        g_hshi[s * (Dm / 2) + i] = 0u;
        g_hslo[s * (Dm / 2) + i] = 0u;
    }
    g_m[d0] = s0 * (1.f / (float)Ss);
    g_m[d0 + 1] = s1 * (1.f / (float)Ss);
}

__global__ void c1_kernel(const float* __restrict__ w1, const float* __restrict__ b1)
{
    int gw = (blockIdx.x * blockDim.x + threadIdx.x) >> 5;
    int lane = threadIdx.x & 31;
    if (gw >= Hh) return;
    const float* wr = w1 + (size_t)gw * (2 * Dm) + Dm;
    float acc = 0.f;
    for (int d = lane; d < Dm; d += 32) acc += g_m[d] * wr[d];
#pragma unroll
    for (int off = 16; off > 0; off >>= 1) acc += __shfl_down_sync(0xffffffffu, acc, off);
    if (lane == 0) g_c1[gw] = acc + b1[gw];
}

// ---------------- top-k(8): 8 tokens/block, batched via toff ---------------
__global__ __launch_bounds__(256) void topk_kernel(const float* __restrict__ tau,
                                                   const float* __restrict__ kp,
                                                   const float* __restrict__ b2,
                                                   int toff)
{
    int t = toff + blockIdx.x * 8 + (threadIdx.x >> 5);
    int lane = threadIdx.x & 31;
    float inv = 1.f / (fabsf(tau[0]) + 0.1f);
    const float* p0 = kp + (size_t)t * 128;
    const float* p1 = kp + (size_t)BT * 128 + (size_t)t * 128;
    float v0 = (p0[lane] + p1[lane] + b2[lane]) * inv;
    float v1 = (p0[lane + 32] + p1[lane + 32] + b2[lane + 32]) * inv;

    float myv = 0.f, vtop = 0.f;
    int myi = 0;
    unsigned long long mk = 0ull;
#pragma unroll
    for (int k = 0; k < Kk; k++) {
        float v; int ii;
        if (v1 > v0) { v = v1; ii = lane + 32; }
        else         { v = v0; ii = lane; }
#pragma unroll
        for (int off = 16; off > 0; off >>= 1) {
            float ov = __shfl_down_sync(0xffffffffu, v, off);
            int   oi = __shfl_down_sync(0xffffffffu, ii, off);
            if (ov > v || (ov == v && oi < ii)) { v = ov; ii = oi; }
        }
        v  = __shfl_sync(0xffffffffu, v, 0);
        ii = __shfl_sync(0xffffffffu, ii, 0);
        if (k == 0) vtop = v;
        if (lane == k) { myv = v; myi = ii; }
        mk |= 1ull << ii;
        if (ii == lane)      v0 = -INFINITY;
        if (ii == lane + 32) v1 = -INFINITY;
    }
    if (lane < Kk) {
        float e = expf(myv - vtop);
        float s = e;
#pragma unroll
        for (int off = 4; off > 0; off >>= 1) s += __shfl_xor_sync(0xffu, s, off);
        g_w8[t * Kk + lane]  = e / s;
        g_idx8[t * Kk + lane] = myi;
    }
    if (lane == 0) g_mask[t] = mk;
}

// ---------------- dispatch: compaction + dense accumulate, batched ---------
__global__ __launch_bounds__(256) void dispatch_chunk_kernel(const float* __restrict__ x,
                                                             int b)
{
    __shared__ float sw[512];
    __shared__ short stl[512];
    __shared__ int warpcnt[8], warpoff[8];
    __shared__ int scnt;
    int blk = blockIdx.x;            // 0..511: s = blk>>3, c = blk&7
    int s = blk >> 3, c = blk & 7;
    int bs = b * 64 + s;
    int tid = threadIdx.x, lane = tid & 31, wid = tid >> 5;
    if (tid == 0) scnt = 0;
    __syncthreads();
    int t0 = c * 512;
#pragma unroll
    for (int pass = 0; pass < 2; pass++) {
        int tl = pass * 256 + tid;
        int t = b * Tt + t0 + tl;
        unsigned long long mk = g_mask[t];
        bool hit = ((mk >> s) & 1ull) != 0ull;
        float w = 0.f;
        if (hit) {
            int base = t * Kk;
#pragma unroll
            for (int k = 0; k < Kk; k++)
                if (g_idx8[base + k] == s) w = g_w8[base + k];
        }
        unsigned bal = __ballot_sync(0xffffffffu, hit);
        int pre = __popc(bal & ((1u << lane) - 1u));
        if (lane == 0) warpcnt[wid] = __popc(bal);
        __syncthreads();
        if (tid == 0) {
            int acc = scnt;
#pragma unroll
            for (int i = 0; i < 8; i++) { warpoff[i] = acc; acc += warpcnt[i]; }
            scnt = acc;
        }
        __syncthreads();
        if (hit) {
            int p = warpoff[wid] + pre;
            sw[p] = w;
            stl[p] = (short)tl;
        }
        __syncthreads();
    }
    int nh = scnt;
    float4 acc = make_float4(0.f, 0.f, 0.f, 0.f);
    float wsum = 0.f;
    const float4* xb = ((const float4*)x) + (size_t)(b * Tt + t0) * (Dm / 4);
    for (int i = 0; i < nh; i++) {
        float w = sw[i];
        int tl = stl[i];
        float4 xv = xb[(size_t)tl * (Dm / 4) + tid];
        acc.x += w * xv.x; acc.y += w * xv.y;
        acc.z += w * xv.z; acc.w += w * xv.w;
        wsum += w;
    }
    ((float4*)g_part)[((size_t)bs * 8 + c) * (Dm / 4) + tid] = acc;
    if (tid == 0) g_pw[bs * 8 + c] = wsum;
}

__global__ __launch_bounds__(256) void dispatch_reduce_kernel(int b)
{
    int bs = b * 64 + blockIdx.x;
    int tid = threadIdx.x;
    float wsum = 0.f;
#pragma unroll
    for (int c = 0; c < 8; c++) wsum += g_pw[bs * 8 + c];
    float4 acc = make_float4(0.f, 0.f, 0.f, 0.f);
#pragma unroll
    for (int c = 0; c < 8; c++) {
        float4 p = ((const float4*)g_part)[((size_t)bs * 8 + c) * (Dm / 4) + tid];
        acc.x += p.x; acc.y += p.y; acc.z += p.z; acc.w += p.w;
    }
    float invw = 1.f / (wsum + 1e-8f);
    acc.x *= invw; acc.y *= invw; acc.z *= invw; acc.w *= invw;
    uint32_t h0, h1, l0, l1;
    split2(acc.x, acc.y, h0, l0);
    split2(acc.z, acc.w, h1, l1);
    size_t o = (size_t)bs * (Dm / 2) + tid * 2;
    g_gihi[o] = h0; g_gihi[o + 1] = h1;
    g_gilo[o] = l0; g_gilo[o + 1] = l1;
}

// ---------------- GRU: reads gx split-K partials ---------------------------
__global__ void gru_kernel(const float* __restrict__ kp, const float* __restrict__ bih)
{
    int i = blockIdx.x * 256 + threadIdx.x;
    int bs = i >> 9, dp = (i & 511) * 2;
    int s = bs & 63;
    const float* gh = g_gh + (size_t)s * (3 * Dm);
    float gx[3][2];
#pragma unroll
    for (int g = 0; g < 3; g++) {
        int c = g * Dm + dp;
        float a0 = bih[c], a1 = bih[c + 1];
#pragma unroll
        for (int z = 0; z < 4; z++) {
            float2 v = *(const float2*)&kp[(size_t)z * 256 * 3 * Dm + (size_t)bs * 3 * Dm + c];
            a0 += v.x; a1 += v.y;
        }
        gx[g][0] = a0; gx[g][1] = a1;
    }
    float out[2];
#pragma unroll
    for (int e = 0; e < 2; e++) {
        int d = dp + e;
        float r = sigm(gx[0][e] + gh[d]);
        float z = sigm(gx[1][e] + gh[Dm + d]);
        float n = tanhf(gx[2][e] + r * gh[2 * Dm + d]);
        out[e] = (1.f - z) * n + z * g_hs[s * Dm + d];
    }
    uint32_t h, l;
    split2(out[0], out[1], h, l);
    g_hnhi[(size_t)bs * (Dm / 2) + (dp >> 1)] = h;
    g_hnlo[(size_t)bs * (Dm / 2) + (dp >> 1)] = l;
}

// ---------------- combine: smem-tiled over g_so ----------------------------
__global__ __launch_bounds__(256) void combine_kernel(float* __restrict__ out)
{
    __shared__ float4 sso[64][32];
    int tc = blockIdx.x, de = blockIdx.y, b = blockIdx.z;
    int tid = threadIdx.x;
    for (int i = tid; i < 64 * 32; i += 256) {
        int s = i >> 5, p = i & 31;
        sso[s][p] = ((const float4*)g_so)[((size_t)(b * 64 + s) * Dm + de * 128) / 4 + p];
    }
    __syncthreads();
    int grp = tid >> 5, p = tid & 31;
    for (int it = 0; it < 32; it++) {
        int tl = it * 8 + grp;
        int t = b * Tt + tc * 256 + tl;
        float4 acc = make_float4(0.f, 0.f, 0.f, 0.f);
#pragma unroll
        for (int k = 0; k < Kk; k++) {
            int s = g_idx8[t * Kk + k];
            float w = g_w8[t * Kk + k];
            float4 v = sso[s][p];
            acc.x += w * v.x; acc.y += w * v.y;
            acc.z += w * v.z; acc.w += w * v.w;
        }
        ((float4*)out)[(size_t)t * (Dm / 4) + de * 32 + p] = acc;
    }
}

// ---------------- launch ----------------------------------------------------
extern "C" void kernel_launch(void* const* d_in, const int* in_sizes, int n_in,
                              void* d_out, int out_size)
{
    const float* x          = (const float*)d_in[0];
    const float* slot_init  = (const float*)d_in[1];
    const float* slot_scale = (const float*)d_in[2];
    const float* w1  = (const float*)d_in[3];
    const float* b1  = (const float*)d_in[4];
    const float* w2  = (const float*)d_in[5];
    const float* b2  = (const float*)d_in[6];
    const float* wih = (const float*)d_in[7];
    const float* whh = (const float*)d_in[8];
    const float* bih = (const float*)d_in[9];
    const float* bhh = (const float*)d_in[10];
    const float* wv  = (const float*)d_in[11];
    const float* bv  = (const float*)d_in[12];
    const float* wo  = (const float*)d_in[13];
    const float* bo  = (const float*)d_in[14];
    const float* tau = (const float*)d_in[15];
    float* out = (float*)d_out;

    // one extra stream only (R12-proven footprint); events are non-timing
    static cudaStream_t s1 = nullptr;
    static cudaEvent_t e0, e1w2, e1side, ehA, ehB, e2;
    if (s1 == nullptr) {
        cudaStreamCreateWithFlags(&s1, cudaStreamNonBlocking);
        cudaEventCreateWithFlags(&e0, cudaEventDisableTiming);
        cudaEventCreateWithFlags(&e1w2, cudaEventDisableTiming);
        cudaEventCreateWithFlags(&e1side, cudaEventDisableTiming);
        cudaEventCreateWithFlags(&ehA, cudaEventDisableTiming);
        cudaEventCreateWithFlags(&ehB, cudaEventDisableTiming);
        cudaEventCreateWithFlags(&e2, cudaEventDisableTiming);
    }

    float *p_c1, *p_gh, *p_so, *p_kp, *p_kp2;
    uint32_t *p_xh, *p_xl, *p_w1h, *p_w1l, *p_w2h, *p_w2l, *p_whhh, *p_whhl,
             *p_wihh, *p_wihl, *p_wvh, *p_wvl, *p_woh, *p_wol,
             *p_hsh, *p_hsl, *p_hh, *p_hl, *p_gih, *p_gil, *p_hnh, *p_hnl,
             *p_svh, *p_svl;
    cudaGetSymbolAddress((void**)&p_c1,  g_c1);
    cudaGetSymbolAddress((void**)&p_gh,  g_gh);
    cudaGetSymbolAddress((void**)&p_so,  g_so);
    cudaGetSymbolAddress((void**)&p_kp,  g_kpart);
    cudaGetSymbolAddress((void**)&p_kp2, g_kpart2);
    cudaGetSymbolAddress((void**)&p_xh,  g_xhi);   cudaGetSymbolAddress((void**)&p_xl,  g_xlo);
    cudaGetSymbolAddress((void**)&p_w1h, g_w1hi);  cudaGetSymbolAddress((void**)&p_w1l, g_w1lo);
    cudaGetSymbolAddress((void**)&p_w2h, g_w2hi);  cudaGetSymbolAddress((void**)&p_w2l, g_w2lo);
    cudaGetSymbolAddress((void**)&p_whhh,g_whhhi); cudaGetSymbolAddress((void**)&p_whhl,g_whhlo);
    cudaGetSymbolAddress((void**)&p_wihh,g_wihhi); cudaGetSymbolAddress((void**)&p_wihl,g_wihlo);
    cudaGetSymbolAddress((void**)&p_wvh, g_wvhi);  cudaGetSymbolAddress((void**)&p_wvl, g_wvlo);
    cudaGetSymbolAddress((void**)&p_woh, g_wohi);  cudaGetSymbolAddress((void**)&p_wol, g_wolo);
    cudaGetSymbolAddress((void**)&p_hsh, g_hshi);  cudaGetSymbolAddress((void**)&p_hsl, g_hslo);
    cudaGetSymbolAddress((void**)&p_hh,  g_hhi);   cudaGetSymbolAddress((void**)&p_hl,  g_hlo);
    cudaGetSymbolAddress((void**)&p_gih, g_gihi);  cudaGetSymbolAddress((void**)&p_gil, g_gilo);
    cudaGetSymbolAddress((void**)&p_hnh, g_hnhi);  cudaGetSymbolAddress((void**)&p_hnl, g_hnlo);
    cudaGetSymbolAddress((void**)&p_svh, g_svhi);  cudaGetSymbolAddress((void**)&p_svl, g_svlo);

    // ---- main: prep, fork side stream ----
    prep_kernel<<<2, 256>>>(slot_init, slot_scale);
    cudaEventRecord(e0, 0);
    cudaStreamWaitEvent(s1, e0, 0);

    // ---- s1: weight conversions + gh chain (off critical path) ----
    convert_kernel<<<(Ss * Hh / 4 + 255) / 256, 256, 0, s1>>>(w2, p_w2h, p_w2l, Ss * Hh / 4);
    cudaEventRecord(e1w2, s1);
    convert_kernel<<<(3 * Dm * Dm / 4 + 255) / 256, 256, 0, s1>>>(whh, p_whhh, p_whhl, 3 * Dm * Dm / 4);
    mma_gemm<<<dim3(24, 1, 4), 256, 0, s1>>>(p_hsh, p_hsl, p_whhh, p_whhl,
                                             nullptr, nullptr, nullptr, nullptr,
                                             Dm, Dm, Dm, 3 * Dm, 0, 256, p_kp2,
                                             0, (size_t)128 * 3 * Dm);
    reduce_epi<<<(128 * 3 * Dm / 2 + 255) / 256, 256, 0, s1>>>(
        p_kp2, 4, (size_t)128 * 3 * Dm, bhh, p_gh, nullptr, nullptr,
        128 * 3 * Dm / 2, 3 * Dm, 0);
    convert_kernel<<<(3 * Dm * Dm / 4 + 255) / 256, 256, 0, s1>>>(wih, p_wihh, p_wihl, 3 * Dm * Dm / 4);
    convert_kernel<<<(Dm * Dm / 4 + 255) / 256, 256, 0, s1>>>(wv, p_wvh, p_wvl, Dm * Dm / 4);
    convert_kernel<<<(Dm * Dm / 4 + 255) / 256, 256, 0, s1>>>(wo, p_woh, p_wol, Dm * Dm / 4);
    cudaEventRecord(e1side, s1);

    // ---- main: critical path: c1, converts, h in two chunks ----
    c1_kernel<<<64, 256>>>(w1, b1);
    convert_kernel<<<(BT * Dm / 4 + 255) / 256, 256>>>(x, p_xh, p_xl, BT * Dm / 4);
    convert_kernel<<<(Hh * 2 * Dm / 4 + 255) / 256, 256>>>(w1, p_w1h, p_w1l, Hh * 2 * Dm / 4);
    // h chunk A: batches 0-1 (rows 0..8191)
    mma_gemm<<<dim3(Hh / 128, 64), 256>>>(p_xh, p_xl, p_w1h, p_w1l,
                                          p_c1, nullptr, p_hh, p_hl,
                                          Dm, Dm, 2 * Dm, Hh, 1, 0, nullptr, 0, 0);
    cudaEventRecord(ehA, 0);
    // h chunk B: batches 2-3 (rows 8192..16383)
    mma_gemm<<<dim3(Hh / 128, 64), 256>>>(p_xh, p_xl, p_w1h, p_w1l,
                                          p_c1, nullptr, p_hh, p_hl,
                                          Dm, Dm, 2 * Dm, Hh, 1, 0, nullptr, 2 * Tt, 0);
    cudaEventRecord(ehB, 0);

    // ---- s1: pipeline batches {0,1} overlapping h chunk B ----
    cudaStreamWaitEvent(s1, e1w2, 0);
    cudaStreamWaitEvent(s1, ehA, 0);
    mma_gemm<<<dim3(1, 64, 2), 256, 0, s1>>>(p_hh, p_hl, p_w2h, p_w2l,
                                             nullptr, nullptr, nullptr, nullptr,
                                             Hh, Hh, Hh, 128, 0, 256, p_kp,
                                             0, (size_t)BT * 128);
    topk_kernel<<<2 * Tt / 8, 256, 0, s1>>>(tau, p_kp, b2, 0);
    dispatch_chunk_kernel<<<512, 256, 0, s1>>>(x, 0);
    dispatch_chunk_kernel<<<512, 256, 0, s1>>>(x, 1);
    dispatch_reduce_kernel<<<64, 256, 0, s1>>>(0);
    dispatch_reduce_kernel<<<64, 256, 0, s1>>>(1);
    // ---- s1: pipeline batches {2,3} after h chunk B ----
    cudaStreamWaitEvent(s1, ehB, 0);
    mma_gemm<<<dim3(1, 64, 2), 256, 0, s1>>>(p_hh, p_hl, p_w2h, p_w2l,
                                             nullptr, nullptr, nullptr, nullptr,
                                             Hh, Hh, Hh, 128, 0, 256, p_kp,
                                             2 * Tt, (size_t)BT * 128);
    topk_kernel<<<2 * Tt / 8, 256, 0, s1>>>(tau, p_kp, b2, 2 * Tt);
    dispatch_chunk_kernel<<<512, 256, 0, s1>>>(x, 2);
    dispatch_chunk_kernel<<<512, 256, 0, s1>>>(x, 3);
    dispatch_reduce_kernel<<<64, 256, 0, s1>>>(2);
    dispatch_reduce_kernel<<<64, 256, 0, s1>>>(3);
    cudaEventRecord(e2, s1);

    // ---- main: slot chain ----
    cudaStreamWaitEvent(0, e2, 0);
    cudaStreamWaitEvent(0, e1side, 0);
    mma_gemm<<<dim3(24, 2, 4), 256>>>(p_gih, p_gil, p_wihh, p_wihl,
                                      nullptr, nullptr, nullptr, nullptr,
                                      Dm, Dm, Dm, 3 * Dm, 0, 256, p_kp,
                                      0, (size_t)256 * 3 * Dm);
    gru_kernel<<<(Bq * Ss * Dm / 2) / 256, 256>>>(p_kp, bih);
    mma_gemm<<<dim3(8, 2, 4), 256>>>(p_hnh, p_hnl, p_wvh, p_wvl,
                                     nullptr, nullptr, nullptr, nullptr,
                                     Dm, Dm, Dm, Dm, 0, 256, p_kp,
                                     0, (size_t)256 * Dm);
    reduce_epi<<<(256 * Dm / 2 + 255) / 256, 256>>>(
        p_kp, 4, (size_t)256 * Dm, bv, nullptr, p_svh, p_svl,
        256 * Dm / 2, Dm, 0);
    mma_gemm<<<dim3(8, 2, 4), 256>>>(p_svh, p_svl, p_woh, p_wol,
                                     nullptr, nullptr, nullptr, nullptr,
                                     Dm, Dm, Dm, Dm, 0, 256, p_kp,
                                     0, (size_t)256 * Dm);
    reduce_epi<<<(256 * Dm / 2 + 255) / 256, 256>>>(
        p_kp, 4, (size_t)256 * Dm, bo, p_so, nullptr, nullptr,
        256 * Dm / 2, Dm, 0);
    combine_kernel<<<dim3(Tt / 256, 8, Bq), 256>>>(out);
}

// round 16
// speedup vs baseline: 1.2392x; 1.2392x over previous
#include <cuda_runtime.h>
#include <cuda_bf16.h>
#include <math.h>
#include <stdint.h>

#define Bq 4
#define Tt 4096
#define Dm 1024
#define Ss 64
#define Kk 8
#define Hh 512
#define BT (Bq*Tt)

// ---------------- scratch (__device__ globals) -----------------------------
__device__ float g_m[Dm];
__device__ float g_hs[Ss*Dm];
__device__ float g_c1[Hh];
__device__ float g_gh[128*3*Dm];
__device__ int   g_idx8[BT*Kk];
__device__ float g_w8[BT*Kk];
__device__ unsigned long long g_mask[BT];
__device__ float g_so[Bq*Ss*Dm];
__device__ float g_part[Bq*Ss*8*Dm];
__device__ float g_pw[Bq*Ss*8];
__device__ float g_kpart[4*BT*128];       // split-K scratch (logits K4; gx/sv/so K8)
__device__ float g_kpart2[4*128*3*Dm];    // split-K scratch for gh (side stream)

// bf16 hi/lo planes
__device__ uint32_t g_xhi[BT*Dm/2],    g_xlo[BT*Dm/2];
__device__ uint32_t g_w1hi[Hh*2*Dm/2], g_w1lo[Hh*2*Dm/2];
__device__ uint32_t g_w2hi[128*Hh/2],  g_w2lo[128*Hh/2];      // pad rows stay 0
__device__ uint32_t g_whhhi[3*Dm*Dm/2],g_whhlo[3*Dm*Dm/2];
__device__ uint32_t g_wihhi[3*Dm*Dm/2],g_wihlo[3*Dm*Dm/2];
__device__ uint32_t g_wvhi[Dm*Dm/2],   g_wvlo[Dm*Dm/2];
__device__ uint32_t g_wohi[Dm*Dm/2],   g_wolo[Dm*Dm/2];
__device__ uint32_t g_hshi[128*Dm/2],  g_hslo[128*Dm/2];
__device__ uint32_t g_hhi[BT*Hh/2],    g_hlo[BT*Hh/2];
__device__ uint32_t g_gihi[Bq*Ss*Dm/2],g_gilo[Bq*Ss*Dm/2];
__device__ uint32_t g_hnhi[Bq*Ss*Dm/2],g_hnlo[Bq*Ss*Dm/2];
__device__ uint32_t g_svhi[Bq*Ss*Dm/2],g_svlo[Bq*Ss*Dm/2];

__device__ __forceinline__ float gelu_exact(float v) {
    return 0.5f * v * (1.f + erff(v * 0.70710678118654752f));
}
__device__ __forceinline__ float sigm(float v) { return 1.f / (1.f + expf(-v)); }

__device__ __forceinline__ void split2(float a, float b, uint32_t& hi, uint32_t& lo) {
    __nv_bfloat16 ah = __float2bfloat16_rn(a);
    __nv_bfloat16 bh = __float2bfloat16_rn(b);
    float ar = a - __bfloat162float(ah);
    float br = b - __bfloat162float(bh);
    __nv_bfloat16 al = __float2bfloat16_rn(ar);
    __nv_bfloat16 bl = __float2bfloat16_rn(br);
    unsigned short ahu = *(unsigned short*)&ah, bhu = *(unsigned short*)&bh;
    unsigned short alu = *(unsigned short*)&al, blu = *(unsigned short*)&bl;
    hi = (uint32_t)ahu | ((uint32_t)bhu << 16);
    lo = (uint32_t)alu | ((uint32_t)blu << 16);
}

// ---------------- mma helper ------------------------------------------------
__device__ __forceinline__ void mma_bf16(float* d, const uint32_t* a,
                                         uint32_t b0, uint32_t b1)
{
    asm volatile(
        "mma.sync.aligned.m16n8k16.row.col.f32.bf16.bf16.f32 "
        "{%0,%1,%2,%3},{%4,%5,%6,%7},{%8,%9},{%0,%1,%2,%3};\n"
        : "+f"(d[0]), "+f"(d[1]), "+f"(d[2]), "+f"(d[3])
        : "r"(a[0]), "r"(a[1]), "r"(a[2]), "r"(a[3]), "r"(b0), "r"(b1));
}

// ---------------- split-bf16 tensor-core GEMM ------------------------------
// roff: extra row offset. zpitch: split-K z-stride (elements). Cpart!=null =>
// split-K mode: blockIdx.z selects K chunk of klen, raw partials out.
__global__ __launch_bounds__(256, 2) void mma_gemm(
    const uint32_t* __restrict__ Ahi, const uint32_t* __restrict__ Alo,
    const uint32_t* __restrict__ Whi, const uint32_t* __restrict__ Wlo,
    const float* __restrict__ bias, float* __restrict__ Cf,
    uint32_t* __restrict__ Chi, uint32_t* __restrict__ Clo,
    int K, int lda, int ldw, int ldc, int act,
    int klen, float* __restrict__ Cpart, int roff, size_t zpitch)
{
    __shared__ uint32_t sA[2][2][8][32][4];
    __shared__ uint32_t sB[2][2][8][32][4];

    int tid = threadIdx.x;
    int lane = tid & 31, warp = tid >> 5;
    int wm = warp >> 2, wn = warp & 3;
    int row0 = roff + blockIdx.y * 128, col0 = blockIdx.x * 128;
    int kbase = Cpart ? blockIdx.z * klen : 0;
    int KK = Cpart ? klen : K;

    float acc[4][4][4];
#pragma unroll
    for (int i = 0; i < 4; i++)
#pragma unroll
        for (int j = 0; j < 4; j++)
#pragma unroll
            for (int r = 0; r < 4; r++) acc[i][j][r] = 0.f;

    uint2 ra[2][2], rb[2][2];
    int r0q = tid >> 2, r1q = (tid + 256) >> 2;
    int kk0 = (tid & 3) * 4;
    int ldua = lda >> 1, lduw = ldw >> 1;

#define LOADG(k0)                                                              \
    {                                                                          \
        size_t a0 = ((size_t)(row0 + r0q) * ldua) + (((k0) + kk0) >> 1);       \
        size_t a1 = ((size_t)(row0 + r1q) * ldua) + (((k0) + kk0) >> 1);       \
        size_t b0 = ((size_t)(col0 + r0q) * lduw) + (((k0) + kk0) >> 1);       \
        size_t b1 = ((size_t)(col0 + r1q) * lduw) + (((k0) + kk0) >> 1);       \
        ra[0][0] = *(const uint2*)(Ahi + a0); ra[0][1] = *(const uint2*)(Alo + a0); \
        ra[1][0] = *(const uint2*)(Ahi + a1); ra[1][1] = *(const uint2*)(Alo + a1); \
        rb[0][0] = *(const uint2*)(Whi + b0); rb[0][1] = *(const uint2*)(Wlo + b0); \
        rb[1][0] = *(const uint2*)(Whi + b1); rb[1][1] = *(const uint2*)(Wlo + b1); \
    }

#define STORES(buf)                                                            \
    {                                                                          \
        _Pragma("unroll")                                                      \
        for (int j = 0; j < 2; j++) {                                          \
            int row = j ? r1q : r0q;                                           \
            int rr = row & 15;                                                 \
            int mt = row >> 4;                                                 \
            int lnA = (rr & 7) * 4 + ((kk0 & 7) >> 1);                         \
            int rgA = (rr >> 3) + 2 * (kk0 >> 3);                              \
            int nt = row >> 3, gg = row & 7;                                   \
            int lnB = gg * 4 + ((kk0 & 7) >> 1);                               \
            int rgB = (nt & 1) * 2 + (kk0 >> 3);                               \
            int ntp = nt >> 1;                                                 \
            _Pragma("unroll")                                                  \
            for (int p = 0; p < 2; p++) {                                      \
                sA[buf][p][mt][lnA][rgA]     = (p ? ra[j][1].x : ra[j][0].x);  \
                sA[buf][p][mt][lnA + 1][rgA] = (p ? ra[j][1].y : ra[j][0].y);  \
                sB[buf][p][ntp][lnB][rgB]     = (p ? rb[j][1].x : rb[j][0].x); \
                sB[buf][p][ntp][lnB + 1][rgB] = (p ? rb[j][1].y : rb[j][0].y); \
            }                                                                  \
        }                                                                      \
    }

    int NK = KK >> 4;
    LOADG(kbase);
    STORES(0);
    __syncthreads();

    for (int ks = 0; ks < NK; ks++) {
        int buf = ks & 1;
        if (ks + 1 < NK) LOADG(kbase + ((ks + 1) << 4));

        uint4 af[4][2];
        uint4 bf[2][2];
#pragma unroll
        for (int mt = 0; mt < 4; mt++) {
            af[mt][0] = *(const uint4*)sA[buf][0][wm * 4 + mt][lane];
            af[mt][1] = *(const uint4*)sA[buf][1][wm * 4 + mt][lane];
        }
#pragma unroll
        for (int i = 0; i < 2; i++) {
            bf[i][0] = *(const uint4*)sB[buf][0][wn * 2 + i][lane];
            bf[i][1] = *(const uint4*)sB[buf][1][wn * 2 + i][lane];
        }
#pragma unroll
        for (int mt = 0; mt < 4; mt++) {
#pragma unroll
            for (int nt = 0; nt < 4; nt++) {
                int ntp = nt >> 1;
                uint32_t bh0, bh1, bl0, bl1;
                if (nt & 1) {
                    bh0 = bf[ntp][0].z; bh1 = bf[ntp][0].w;
                    bl0 = bf[ntp][1].z; bl1 = bf[ntp][1].w;
                } else {
                    bh0 = bf[ntp][0].x; bh1 = bf[ntp][0].y;
                    bl0 = bf[ntp][1].x; bl1 = bf[ntp][1].y;
                }
                mma_bf16(acc[mt][nt], (const uint32_t*)&af[mt][0], bh0, bh1);
                mma_bf16(acc[mt][nt], (const uint32_t*)&af[mt][0], bl0, bl1);
                mma_bf16(acc[mt][nt], (const uint32_t*)&af[mt][1], bh0, bh1);
            }
        }
        if (ks + 1 < NK) {
            __syncthreads();
            STORES(buf ^ 1);
            __syncthreads();
        }
    }

    int g = lane >> 2, t4 = lane & 3;
    int lduc = ldc >> 1;
    if (Cpart) {
        size_t zoff = (size_t)blockIdx.z * zpitch;
#pragma unroll
        for (int mt = 0; mt < 4; mt++) {
            int r0 = row0 + wm * 64 + mt * 16 + g;
#pragma unroll
            for (int nt = 0; nt < 4; nt++) {
                int c = col0 + wn * 32 + nt * 8 + t4 * 2;
                *(float2*)&Cpart[zoff + (size_t)r0 * ldc + c] =
                    make_float2(acc[mt][nt][0], acc[mt][nt][1]);
                *(float2*)&Cpart[zoff + (size_t)(r0 + 8) * ldc + c] =
                    make_float2(acc[mt][nt][2], acc[mt][nt][3]);
            }
        }
        return;
    }
#pragma unroll
    for (int mt = 0; mt < 4; mt++) {
        int r0 = row0 + wm * 64 + mt * 16 + g;
#pragma unroll
        for (int nt = 0; nt < 4; nt++) {
            int c = col0 + wn * 32 + nt * 8 + t4 * 2;
            float bb0 = bias[c], bb1 = bias[c + 1];
            float v0 = acc[mt][nt][0] + bb0;
            float v1 = acc[mt][nt][1] + bb1;
            float v2 = acc[mt][nt][2] + bb0;
            float v3 = acc[mt][nt][3] + bb1;
            if (act) {
                v0 = gelu_exact(v0); v1 = gelu_exact(v1);
                v2 = gelu_exact(v2); v3 = gelu_exact(v3);
            }
            if (Cf) {
                *(float2*)&Cf[(size_t)r0 * ldc + c] = make_float2(v0, v1);
                *(float2*)&Cf[(size_t)(r0 + 8) * ldc + c] = make_float2(v2, v3);
            }
            if (Chi) {
                uint32_t h, l;
                split2(v0, v1, h, l);
                size_t o = (size_t)r0 * lduc + (c >> 1);
                Chi[o] = h; Clo[o] = l;
                split2(v2, v3, h, l);
                o = (size_t)(r0 + 8) * lduc + (c >> 1);
                Chi[o] = h; Clo[o] = l;
            }
        }
    }
#undef LOADG
#undef STORES
}

// ---------------- split-K reduce + epilogue --------------------------------
__global__ __launch_bounds__(256) void reduce_epi(
    const float* __restrict__ part, int nz, size_t zstride,
    const float* __restrict__ bias, float* __restrict__ Cf,
    uint32_t* __restrict__ Chi, uint32_t* __restrict__ Clo,
    int npairs, int N, int act)
{
    int idx = blockIdx.x * 256 + threadIdx.x;
    if (idx >= npairs) return;
    int half = N >> 1;
    int r = idx / half, cp = idx - r * half;
    int c = cp * 2;
    size_t o = (size_t)r * N + c;
    float s0 = 0.f, s1 = 0.f;
    for (int z = 0; z < nz; z++) {
        float2 v = *(const float2*)&part[z * zstride + o];
        s0 += v.x; s1 += v.y;
    }
    s0 += bias[c]; s1 += bias[c + 1];
    if (act) { s0 = gelu_exact(s0); s1 = gelu_exact(s1); }
    if (Cf) *(float2*)&Cf[o] = make_float2(s0, s1);
    if (Chi) {
        uint32_t h, l;
        split2(s0, s1, h, l);
        Chi[(size_t)r * half + cp] = h;
        Clo[(size_t)r * half + cp] = l;
    }
}

// ---------------- fp32 -> hi/lo plane conversion ---------------------------
__global__ void convert_kernel(const float* __restrict__ s,
                               uint32_t* __restrict__ hi, uint32_t* __restrict__ lo,
                               int n4)
{
    int i = blockIdx.x * 256 + threadIdx.x;
    if (i >= n4) return;
    float4 v = ((const float4*)s)[i];
    uint32_t h0, h1, l0, l1;
    split2(v.x, v.y, h0, l0);
    split2(v.z, v.w, h1, l1);
    hi[2*i] = h0; hi[2*i+1] = h1;
    lo[2*i] = l0; lo[2*i+1] = l1;
}

// ---------------- prep (includes hs pad zeroing) ---------------------------
__global__ void prep_kernel(const float* __restrict__ slot_init,
                            const float* __restrict__ slot_scale)
{
    int i = blockIdx.x * 256 + threadIdx.x;
    int d0 = i * 2;
    float s0 = 0.f, s1 = 0.f;
    for (int s = 0; s < Ss; s++) {
        float sc = slot_scale[s];
        float a0 = slot_init[s * Dm + d0] * sc;
        float a1 = slot_init[s * Dm + d0 + 1] * sc;
        g_hs[s * Dm + d0] = a0;
        g_hs[s * Dm + d0 + 1] = a1;
        uint32_t h, l;
        split2(a0, a1, h, l);
        g_hshi[s * (Dm / 2) + i] = h;
        g_hslo[s * (Dm / 2) + i] = l;
        s0 += a0; s1 += a1;
    }
    for (int s = 64; s < 128; s++) {
        g_hshi[s * (Dm / 2) + i] = 0u;
        g_hslo[s * (Dm / 2) + i] = 0u;
    }
    g_m[d0] = s0 * (1.f / (float)Ss);
    g_m[d0 + 1] = s1 * (1.f / (float)Ss);
}

__global__ void c1_kernel(const float* __restrict__ w1, const float* __restrict__ b1)
{
    int gw = (blockIdx.x * blockDim.x + threadIdx.x) >> 5;
    int lane = threadIdx.x & 31;
    if (gw >= Hh) return;
    const float* wr = w1 + (size_t)gw * (2 * Dm) + Dm;
    float acc = 0.f;
    for (int d = lane; d < Dm; d += 32) acc += g_m[d] * wr[d];
#pragma unroll
    for (int off = 16; off > 0; off >>= 1) acc += __shfl_down_sync(0xffffffffu, acc, off);
    if (lane == 0) g_c1[gw] = acc + b1[gw];
}

// ---------------- top-k(8): 8 tokens/block, sums 4 logits partials ---------
__global__ __launch_bounds__(256) void topk_kernel(const float* __restrict__ tau,
                                                   const float* __restrict__ kp,
                                                   const float* __restrict__ b2)
{
    int t = blockIdx.x * 8 + (threadIdx.x >> 5);
    int lane = threadIdx.x & 31;
    float inv = 1.f / (fabsf(tau[0]) + 0.1f);
    float v0 = b2[lane], v1 = b2[lane + 32];
#pragma unroll
    for (int z = 0; z < 4; z++) {
        const float* p = kp + (size_t)z * BT * 128 + (size_t)t * 128;
        v0 += p[lane];
        v1 += p[lane + 32];
    }
    v0 *= inv; v1 *= inv;

    float myv = 0.f, vtop = 0.f;
    int myi = 0;
    unsigned long long mk = 0ull;
#pragma unroll
    for (int k = 0; k < Kk; k++) {
        float v; int ii;
        if (v1 > v0) { v = v1; ii = lane + 32; }
        else         { v = v0; ii = lane; }
#pragma unroll
        for (int off = 16; off > 0; off >>= 1) {
            float ov = __shfl_down_sync(0xffffffffu, v, off);
            int   oi = __shfl_down_sync(0xffffffffu, ii, off);
            if (ov > v || (ov == v && oi < ii)) { v = ov; ii = oi; }
        }
        v  = __shfl_sync(0xffffffffu, v, 0);
        ii = __shfl_sync(0xffffffffu, ii, 0);
        if (k == 0) vtop = v;
        if (lane == k) { myv = v; myi = ii; }
        mk |= 1ull << ii;
        if (ii == lane)      v0 = -INFINITY;
        if (ii == lane + 32) v1 = -INFINITY;
    }
    if (lane < Kk) {
        float e = expf(myv - vtop);
        float s = e;
#pragma unroll
        for (int off = 4; off > 0; off >>= 1) s += __shfl_xor_sync(0xffu, s, off);
        g_w8[t * Kk + lane]  = e / s;
        g_idx8[t * Kk + lane] = myi;
    }
    if (lane == 0) g_mask[t] = mk;
}

// ---------------- dispatch: compaction + dense accumulate ------------------
__global__ __launch_bounds__(256) void dispatch_chunk_kernel(const float* __restrict__ x)
{
    __shared__ float sw[512];
    __shared__ short stl[512];
    __shared__ int warpcnt[8], warpoff[8];
    __shared__ int scnt;
    int blk = blockIdx.x;
    int bs = blk >> 3, c = blk & 7;
    int b = bs >> 6, s = bs & 63;
    int tid = threadIdx.x, lane = tid & 31, wid = tid >> 5;
    if (tid == 0) scnt = 0;
    __syncthreads();
    int t0 = c * 512;
#pragma unroll
    for (int pass = 0; pass < 2; pass++) {
        int tl = pass * 256 + tid;
        int t = b * Tt + t0 + tl;
        unsigned long long mk = g_mask[t];
        bool hit = ((mk >> s) & 1ull) != 0ull;
        float w = 0.f;
        if (hit) {
            int base = t * Kk;
#pragma unroll
            for (int k = 0; k < Kk; k++)
                if (g_idx8[base + k] == s) w = g_w8[base + k];
        }
        unsigned bal = __ballot_sync(0xffffffffu, hit);
        int pre = __popc(bal & ((1u << lane) - 1u));
        if (lane == 0) warpcnt[wid] = __popc(bal);
        __syncthreads();
        if (tid == 0) {
            int acc = scnt;
#pragma unroll
            for (int i = 0; i < 8; i++) { warpoff[i] = acc; acc += warpcnt[i]; }
            scnt = acc;
        }
        __syncthreads();
        if (hit) {
            int p = warpoff[wid] + pre;
            sw[p] = w;
            stl[p] = (short)tl;
        }
        __syncthreads();
    }
    int nh = scnt;
    float4 acc = make_float4(0.f, 0.f, 0.f, 0.f);
    float wsum = 0.f;
    const float4* xb = ((const float4*)x) + (size_t)(b * Tt + t0) * (Dm / 4);
    for (int i = 0; i < nh; i++) {
        float w = sw[i];
        int tl = stl[i];
        float4 xv = xb[(size_t)tl * (Dm / 4) + tid];
        acc.x += w * xv.x; acc.y += w * xv.y;
        acc.z += w * xv.z; acc.w += w * xv.w;
        wsum += w;
    }
    ((float4*)g_part)[((size_t)bs * 8 + c) * (Dm / 4) + tid] = acc;
    if (tid == 0) g_pw[bs * 8 + c] = wsum;
}

__global__ __launch_bounds__(256) void dispatch_reduce_kernel()
{
    int bs = blockIdx.x;
    int tid = threadIdx.x;
    float wsum = 0.f;
#pragma unroll
    for (int c = 0; c < 8; c++) wsum += g_pw[bs * 8 + c];
    float4 acc = make_float4(0.f, 0.f, 0.f, 0.f);
#pragma unroll
    for (int c = 0; c < 8; c++) {
        float4 p = ((const float4*)g_part)[((size_t)bs * 8 + c) * (Dm / 4) + tid];
        acc.x += p.x; acc.y += p.y; acc.z += p.z; acc.w += p.w;
    }
    float invw = 1.f / (wsum + 1e-8f);
    acc.x *= invw; acc.y *= invw; acc.z *= invw; acc.w *= invw;
    uint32_t h0, h1, l0, l1;
    split2(acc.x, acc.y, h0, l0);
    split2(acc.z, acc.w, h1, l1);
    size_t o = (size_t)bs * (Dm / 2) + tid * 2;
    g_gihi[o] = h0; g_gihi[o + 1] = h1;
    g_gilo[o] = l0; g_gilo[o + 1] = l1;
}

// ---------------- GRU: sums 8 gx split-K partials --------------------------
__global__ void gru_kernel(const float* __restrict__ kp, const float* __restrict__ bih)
{
    int i = blockIdx.x * 256 + threadIdx.x;
    int bs = i >> 9, dp = (i & 511) * 2;
    int s = bs & 63;
    const float* gh = g_gh + (size_t)s * (3 * Dm);
    float gx[3][2];
#pragma unroll
    for (int g = 0; g < 3; g++) {
        int c = g * Dm + dp;
        float a0 = bih[c], a1 = bih[c + 1];
#pragma unroll
        for (int z = 0; z < 8; z++) {
            float2 v = *(const float2*)&kp[(size_t)z * 256 * 3 * Dm + (size_t)bs * 3 * Dm + c];
            a0 += v.x; a1 += v.y;
        }
        gx[g][0] = a0; gx[g][1] = a1;
    }
    float out[2];
#pragma unroll
    for (int e = 0; e < 2; e++) {
        int d = dp + e;
        float r = sigm(gx[0][e] + gh[d]);
        float z = sigm(gx[1][e] + gh[Dm + d]);
        float n = tanhf(gx[2][e] + r * gh[2 * Dm + d]);
        out[e] = (1.f - z) * n + z * g_hs[s * Dm + d];
    }
    uint32_t h, l;
    split2(out[0], out[1], h, l);
    g_hnhi[(size_t)bs * (Dm / 2) + (dp >> 1)] = h;
    g_hnlo[(size_t)bs * (Dm / 2) + (dp >> 1)] = l;
}

// ---------------- combine: smem-tiled over g_so ----------------------------
__global__ __launch_bounds__(256) void combine_kernel(float* __restrict__ out)
{
    __shared__ float4 sso[64][32];
    int tc = blockIdx.x, de = blockIdx.y, b = blockIdx.z;
    int tid = threadIdx.x;
    for (int i = tid; i < 64 * 32; i += 256) {
        int s = i >> 5, p = i & 31;
        sso[s][p] = ((const float4*)g_so)[((size_t)(b * 64 + s) * Dm + de * 128) / 4 + p];
    }
    __syncthreads();
    int grp = tid >> 5, p = tid & 31;
    for (int it = 0; it < 32; it++) {
        int tl = it * 8 + grp;
        int t = b * Tt + tc * 256 + tl;
        float4 acc = make_float4(0.f, 0.f, 0.f, 0.f);
#pragma unroll
        for (int k = 0; k < Kk; k++) {
            int s = g_idx8[t * Kk + k];
            float w = g_w8[t * Kk + k];
            float4 v = sso[s][p];
            acc.x += w * v.x; acc.y += w * v.y;
            acc.z += w * v.z; acc.w += w * v.w;
        }
        ((float4*)out)[(size_t)t * (Dm / 4) + de * 32 + p] = acc;
    }
}

// ---------------- launch ----------------------------------------------------
extern "C" void kernel_launch(void* const* d_in, const int* in_sizes, int n_in,
                              void* d_out, int out_size)
{
    const float* x          = (const float*)d_in[0];
    const float* slot_init  = (const float*)d_in[1];
    const float* slot_scale = (const float*)d_in[2];
    const float* w1  = (const float*)d_in[3];
    const float* b1  = (const float*)d_in[4];
    const float* w2  = (const float*)d_in[5];
    const float* b2  = (const float*)d_in[6];
    const float* wih = (const float*)d_in[7];
    const float* whh = (const float*)d_in[8];
    const float* bih = (const float*)d_in[9];
    const float* bhh = (const float*)d_in[10];
    const float* wv  = (const float*)d_in[11];
    const float* bv  = (const float*)d_in[12];
    const float* wo  = (const float*)d_in[13];
    const float* bo  = (const float*)d_in[14];
    const float* tau = (const float*)d_in[15];
    float* out = (float*)d_out;

    static cudaStream_t s1 = nullptr;
    static cudaEvent_t e0, e1w2, e1side;
    if (s1 == nullptr) {
        cudaStreamCreateWithFlags(&s1, cudaStreamNonBlocking);
        cudaEventCreateWithFlags(&e0, cudaEventDisableTiming);
        cudaEventCreateWithFlags(&e1w2, cudaEventDisableTiming);
        cudaEventCreateWithFlags(&e1side, cudaEventDisableTiming);
    }

    float *p_c1, *p_gh, *p_so, *p_kp, *p_kp2;
    uint32_t *p_xh, *p_xl, *p_w1h, *p_w1l, *p_w2h, *p_w2l, *p_whhh, *p_whhl,
             *p_wihh, *p_wihl, *p_wvh, *p_wvl, *p_woh, *p_wol,
             *p_hsh, *p_hsl, *p_hh, *p_hl, *p_gih, *p_gil, *p_hnh, *p_hnl,
             *p_svh, *p_svl;
    cudaGetSymbolAddress((void**)&p_c1,  g_c1);
    cudaGetSymbolAddress((void**)&p_gh,  g_gh);
    cudaGetSymbolAddress((void**)&p_so,  g_so);
    cudaGetSymbolAddress((void**)&p_kp,  g_kpart);
    cudaGetSymbolAddress((void**)&p_kp2, g_kpart2);
    cudaGetSymbolAddress((void**)&p_xh,  g_xhi);   cudaGetSymbolAddress((void**)&p_xl,  g_xlo);
    cudaGetSymbolAddress((void**)&p_w1h, g_w1hi);  cudaGetSymbolAddress((void**)&p_w1l, g_w1lo);
    cudaGetSymbolAddress((void**)&p_w2h, g_w2hi);  cudaGetSymbolAddress((void**)&p_w2l, g_w2lo);
    cudaGetSymbolAddress((void**)&p_whhh,g_whhhi); cudaGetSymbolAddress((void**)&p_whhl,g_whhlo);
    cudaGetSymbolAddress((void**)&p_wihh,g_wihhi); cudaGetSymbolAddress((void**)&p_wihl,g_wihlo);
    cudaGetSymbolAddress((void**)&p_wvh, g_wvhi);  cudaGetSymbolAddress((void**)&p_wvl, g_wvlo);
    cudaGetSymbolAddress((void**)&p_woh, g_wohi);  cudaGetSymbolAddress((void**)&p_wol, g_wolo);
    cudaGetSymbolAddress((void**)&p_hsh, g_hshi);  cudaGetSymbolAddress((void**)&p_hsl, g_hslo);
    cudaGetSymbolAddress((void**)&p_hh,  g_hhi);   cudaGetSymbolAddress((void**)&p_hl,  g_hlo);
    cudaGetSymbolAddress((void**)&p_gih, g_gihi);  cudaGetSymbolAddress((void**)&p_gil, g_gilo);
    cudaGetSymbolAddress((void**)&p_hnh, g_hnhi);  cudaGetSymbolAddress((void**)&p_hnl, g_hnlo);
    cudaGetSymbolAddress((void**)&p_svh, g_svhi);  cudaGetSymbolAddress((void**)&p_svl, g_svlo);

    // ---- main: prep, fork side stream ----
    prep_kernel<<<2, 256>>>(slot_init, slot_scale);
    cudaEventRecord(e0, 0);
    cudaStreamWaitEvent(s1, e0, 0);

    // ---- s1: weight conversions + gh chain ----
    convert_kernel<<<(Ss * Hh / 4 + 255) / 256, 256, 0, s1>>>(w2, p_w2h, p_w2l, Ss * Hh / 4);
    cudaEventRecord(e1w2, s1);
    convert_kernel<<<(3 * Dm * Dm / 4 + 255) / 256, 256, 0, s1>>>(whh, p_whhh, p_whhl, 3 * Dm * Dm / 4);
    mma_gemm<<<dim3(24, 1, 4), 256, 0, s1>>>(p_hsh, p_hsl, p_whhh, p_whhl,
                                             nullptr, nullptr, nullptr, nullptr,
                                             Dm, Dm, Dm, 3 * Dm, 0, 256, p_kp2,
                                             0, (size_t)128 * 3 * Dm);
    reduce_epi<<<(128 * 3 * Dm / 2 + 255) / 256, 256, 0, s1>>>(
        p_kp2, 4, (size_t)128 * 3 * Dm, bhh, p_gh, nullptr, nullptr,
        128 * 3 * Dm / 2, 3 * Dm, 0);
    convert_kernel<<<(3 * Dm * Dm / 4 + 255) / 256, 256, 0, s1>>>(wih, p_wihh, p_wihl, 3 * Dm * Dm / 4);
    convert_kernel<<<(Dm * Dm / 4 + 255) / 256, 256, 0, s1>>>(wv, p_wvh, p_wvl, Dm * Dm / 4);
    convert_kernel<<<(Dm * Dm / 4 + 255) / 256, 256, 0, s1>>>(wo, p_woh, p_wol, Dm * Dm / 4);
    cudaEventRecord(e1side, s1);

    // ---- main: critical path ----
    c1_kernel<<<64, 256>>>(w1, b1);
    convert_kernel<<<(BT * Dm / 4 + 255) / 256, 256>>>(x, p_xh, p_xl, BT * Dm / 4);
    convert_kernel<<<(Hh * 2 * Dm / 4 + 255) / 256, 256>>>(w1, p_w1h, p_w1l, Hh * 2 * Dm / 4);
    // h = gelu(x @ w1[:, :D]^T + c1)  (16384 x 512) -> bf16 planes
    mma_gemm<<<dim3(Hh / 128, BT / 128), 256>>>(p_xh, p_xl, p_w1h, p_w1l,
                                                p_c1, nullptr, p_hh, p_hl,
                                                Dm, Dm, 2 * Dm, Hh, 1, 0, nullptr, 0, 0);
    cudaStreamWaitEvent(0, e1w2, 0);
    // logits = h @ w2pad^T  (16384 x 128, K=512) split-K4, partials only
    mma_gemm<<<dim3(1, BT / 128, 4), 256>>>(p_hh, p_hl, p_w2h, p_w2l,
                                            nullptr, nullptr, nullptr, nullptr,
                                            Hh, Hh, Hh, 128, 0, 128, p_kp,
                                            0, (size_t)BT * 128);
    topk_kernel<<<BT / 8, 256>>>(tau, p_kp, b2);
    dispatch_chunk_kernel<<<Bq * Ss * 8, 256>>>(x);
    dispatch_reduce_kernel<<<Bq * Ss, 256>>>();
    cudaStreamWaitEvent(0, e1side, 0);
    // gx = gi @ wih^T  (256 x 3072, K=1024) split-K8, partials only
    mma_gemm<<<dim3(24, 2, 8), 256>>>(p_gih, p_gil, p_wihh, p_wihl,
                                      nullptr, nullptr, nullptr, nullptr,
                                      Dm, Dm, Dm, 3 * Dm, 0, 128, p_kp,
                                      0, (size_t)256 * 3 * Dm);
    gru_kernel<<<(Bq * Ss * Dm / 2) / 256, 256>>>(p_kp, bih);
    // sv = h_new @ wv^T + bv  (256 x 1024, K=1024) split-K8 -> bf16 planes
    mma_gemm<<<dim3(8, 2, 8), 256>>>(p_hnh, p_hnl, p_wvh, p_wvl,
                                     nullptr, nullptr, nullptr, nullptr,
                                     Dm, Dm, Dm, Dm, 0, 128, p_kp,
                                     0, (size_t)256 * Dm);
    reduce_epi<<<(256 * Dm / 2 + 255) / 256, 256>>>(
        p_kp, 8, (size_t)256 * Dm, bv, nullptr, p_svh, p_svl,
        256 * Dm / 2, Dm, 0);
    // so = sv @ wo^T + bo  (256 x 1024, K=1024) split-K8 -> fp32 g_so
    mma_gemm<<<dim3(8, 2, 8), 256>>>(p_svh, p_svl, p_woh, p_wol,
                                     nullptr, nullptr, nullptr, nullptr,
                                     Dm, Dm, Dm, Dm, 0, 128, p_kp,
                                     0, (size_t)256 * Dm);
    reduce_epi<<<(256 * Dm / 2 + 255) / 256, 256>>>(
        p_kp, 8, (size_t)256 * Dm, bo, p_so, nullptr, nullptr,
        256 * Dm / 2, Dm, 0);
    // combine: smem-tiled gather over g_so
    combine_kernel<<<dim3(Tt / 256, 8, Bq), 256>>>(out);
}